// round 10
// baseline (speedup 1.0000x reference)
#include <cuda_runtime.h>
#include <cuda_bf16.h>
#include <math.h>
#include <cstdint>

#define NN 4096
#define MM 8192
#define DD 128
#define NTILE 64
#define NCTAS 1056   // sum over rt of (32 - rt/2)

// operands pre-scaled by sqrt(10 * log2(e)) so acc = log2(e) * sim / T
#define SCALE_IN 3.798282100420615f
#define CB2 14.426950408889634f          // 10 * log2(e)
#define LN2 0.6931471805599453f

// ---------------- device globals (no allocs allowed) ----------------------
__device__ __align__(16) __nv_bfloat16 g_zbf[MM * DD];
__device__ float g_rowsum[MM];
__device__ float g_partner[NN];   // log2e * sim[i, i+N] / T
__device__ unsigned int g_done;

// ---------------- helpers --------------------------------------------------
__device__ __forceinline__ uint32_t smem_to_u32(const void* p) {
    uint32_t a;
    asm("{ .reg .u64 t; cvta.to.shared.u64 t, %1; cvt.u32.u64 %0, t; }"
        : "=r"(a) : "l"(p));
    return a;
}

#define LDSM_X4(r0, r1, r2, r3, addr)                                          \
    asm volatile("ldmatrix.sync.aligned.m8n8.x4.shared.b16 {%0,%1,%2,%3}, [%4];" \
        : "=r"(r0), "=r"(r1), "=r"(r2), "=r"(r3) : "r"(addr))

#define MMA16816(d, a0, a1, a2, a3, b0, b1)                                    \
    asm volatile("mma.sync.aligned.m16n8k16.row.col.f32.bf16.bf16.f32 "        \
        "{%0,%1,%2,%3}, {%4,%5,%6,%7}, {%8,%9}, {%0,%1,%2,%3};"                \
        : "+f"((d)[0]), "+f"((d)[1]), "+f"((d)[2]), "+f"((d)[3])               \
        : "r"(a0), "r"(a1), "r"(a2), "r"(a3), "r"(b0), "r"(b1))

#define CP_ASYNC16(sm, gp)                                                     \
    asm volatile("cp.async.cg.shared.global [%0], [%1], 16;"                   \
        :: "r"(sm), "l"(gp) : "memory")
#define CP_COMMIT  asm volatile("cp.async.commit_group;" ::: "memory")
#define CP_WAIT(n) asm volatile("cp.async.wait_group %0;" :: "n"(n) : "memory")

// ---------------------------------------------------------------------------
// Kernel 1: warp handles paired rows r (z1) and r+NN (z2).
// Zeroes g_rowsum and g_done.
// ---------------------------------------------------------------------------
__global__ void __launch_bounds__(512) normalize_kernel(
        const float* __restrict__ z1, const float* __restrict__ z2) {
    int r = (blockIdx.x * 512 + threadIdx.x) >> 5;   // 0..NN-1
    int lane = threadIdx.x & 31;
    if (blockIdx.x == 0 && threadIdx.x == 0) g_done = 0;
    float4 a = ((const float4*)(z1 + (size_t)r * DD))[lane];
    float4 b = ((const float4*)(z2 + (size_t)r * DD))[lane];
    float sa = a.x * a.x + a.y * a.y + a.z * a.z + a.w * a.w;
    float sb = b.x * b.x + b.y * b.y + b.z * b.z + b.w * b.w;
    #pragma unroll
    for (int o = 16; o; o >>= 1) {
        sa += __shfl_xor_sync(0xffffffffu, sa, o);
        sb += __shfl_xor_sync(0xffffffffu, sb, o);
    }
    float ia = SCALE_IN * rsqrtf(sa);
    float ib = SCALE_IN * rsqrtf(sb);
    __nv_bfloat162 a0 = {__float2bfloat16(a.x * ia), __float2bfloat16(a.y * ia)};
    __nv_bfloat162 a1 = {__float2bfloat16(a.z * ia), __float2bfloat16(a.w * ia)};
    __nv_bfloat162 b0 = {__float2bfloat16(b.x * ib), __float2bfloat16(b.y * ib)};
    __nv_bfloat162 b1 = {__float2bfloat16(b.z * ib), __float2bfloat16(b.w * ib)};
    uint2 oa, ob;
    oa.x = *(uint32_t*)&a0; oa.y = *(uint32_t*)&a1;
    ob.x = *(uint32_t*)&b0; ob.y = *(uint32_t*)&b1;
    ((uint2*)(g_zbf + (size_t)r * DD))[lane] = oa;
    ((uint2*)(g_zbf + (size_t)(r + NN) * DD))[lane] = ob;
    if (lane == 0) { g_rowsum[r] = 0.0f; g_rowsum[r + NN] = 0.0f; }
}

// ---------------------------------------------------------------------------
// Fragment load for one k-step (6 LDSM.x4)
// ---------------------------------------------------------------------------
__device__ __forceinline__ void ldsm_frags(
        const uint32_t* baseA, const uint32_t* baseBp,
        uint32_t xorA, uint32_t xorB, int kbA_half, int kbB_half, int ks,
        uint32_t (*a)[4], uint32_t (*b)[2]) {
    uint32_t kbA = (uint32_t)((ks * 2 + kbA_half) * 16);
    #pragma unroll
    for (int mi = 0; mi < 4; mi++)
        LDSM_X4(a[mi][0], a[mi][1], a[mi][2], a[mi][3], baseA[mi] + (kbA ^ xorA));
    uint32_t kbB = (uint32_t)((ks * 2 + kbB_half) * 16);
    #pragma unroll
    for (int pi = 0; pi < 2; pi++)
        LDSM_X4(b[2 * pi][0], b[2 * pi][1], b[2 * pi + 1][0], b[2 * pi + 1][1],
                baseBp[pi] + (kbB ^ xorB));
}

__device__ __forceinline__ void mma_step(float (*acc)[4][4],
                                         uint32_t (*a)[4], uint32_t (*b)[2]) {
    #pragma unroll
    for (int mi = 0; mi < 4; mi++)
        #pragma unroll
        for (int ni = 0; ni < 4; ni++)
            MMA16816(acc[mi][ni], a[mi][0], a[mi][1], a[mi][2], a[mi][3],
                     b[ni][0], b[ni][1]);
}

// Pipelined 8-k-step tile GEMM with register double-buffered fragments.
__device__ __forceinline__ void gemm_tile(
        const uint32_t* baseA, const uint32_t* baseBp,
        uint32_t xorA, uint32_t xorB, int kbA_half, int kbB_half,
        float (*acc)[4][4]) {
    uint32_t afr[2][4][4], bfr[2][4][2];
    ldsm_frags(baseA, baseBp, xorA, xorB, kbA_half, kbB_half, 0, afr[0], bfr[0]);
    #pragma unroll
    for (int ks = 0; ks < 8; ks++) {
        int cur = ks & 1, nxt = cur ^ 1;
        if (ks < 7)
            ldsm_frags(baseA, baseBp, xorA, xorB, kbA_half, kbB_half, ks + 1,
                       afr[nxt], bfr[nxt]);
        mma_step(acc, afr[cur], bfr[cur]);
    }
}

// ---------------------------------------------------------------------------
// Kernel 2: 128x256 slab per CTA (two 128x128 tiles sharing one A tile),
// upper-triangular coverage, fused exp2 epilogue, last-CTA finalize.
// smem: A 32K | B0 32K | B1 32K | colscr0 1K | colscr1 1K | rowscr 2K
// ---------------------------------------------------------------------------
__global__ void __launch_bounds__(256, 2) sim_kernel(float* __restrict__ out) {
    int rt = 0, rem = blockIdx.x;
    #pragma unroll 1
    while (rem >= 32 - (rt >> 1)) { rem -= 32 - (rt >> 1); rt++; }
    int ctp = (rt >> 1) + rem;
    int ct0 = 2 * ctp, ct1 = ct0 + 1;
    // modes: 0=skip, 1=diag, 2=pblock, 3=plain
    int m0 = (ct0 < rt) ? 0 : (ct0 == rt) ? 1 : (ct0 == rt + 32) ? 2 : 3;
    int m1 = (ct1 == rt) ? 1 : (ct1 == rt + 32) ? 2 : 3;

    extern __shared__ __align__(128) unsigned char smem[];
    uint32_t sb = smem_to_u32(smem);
    uint32_t smA = sb, smB0 = sb + 32768, smB1 = sb + 65536;
    float* colscr0 = (float*)(smem + 98304);
    float* colscr1 = (float*)(smem + 99328);
    float* rowscr  = (float*)(smem + 100352);

    int tid = threadIdx.x;
    int lane = tid & 31, wid = tid >> 5;
    int wr = wid >> 2, wc = wid & 3;        // 2x4 warps; warp tile 64r x 32c
    int row0 = rt * 128;
    int col0_0 = ct0 * 128, col0_1 = ct1 * 128;

    // ---- async loads: group0 = {A, B0}, group1 = {B1} ----
    {
        const uint4* srcA  = (const uint4*)(g_zbf + (size_t)row0 * DD);
        const uint4* srcB0 = (const uint4*)(g_zbf + (size_t)col0_0 * DD);
        const uint4* srcB1 = (const uint4*)(g_zbf + (size_t)col0_1 * DD);
        #pragma unroll
        for (int j = 0; j < 8; j++) {
            int s = tid + 256 * j;          // 0..2047
            int r = s >> 4, kb = s & 15;
            uint32_t off = (uint32_t)(r * 256) + (uint32_t)((kb * 16) ^ ((r & 7) * 16));
            CP_ASYNC16(smA + off, srcA + s);
            CP_ASYNC16(smB0 + off, srcB0 + s);
        }
        CP_COMMIT;
        #pragma unroll
        for (int j = 0; j < 8; j++) {
            int s = tid + 256 * j;
            int r = s >> 4, kb = s & 15;
            uint32_t off = (uint32_t)(r * 256) + (uint32_t)((kb * 16) ^ ((r & 7) * 16));
            CP_ASYNC16(smB1 + off, srcB1 + s);
        }
        CP_COMMIT;
    }

    // ---- fragment addresses ----
    int rA = wr * 64 + (lane & 7) + ((lane >> 3) & 1) * 8;
    uint32_t xorA = (uint32_t)((rA & 7) << 4);
    int kbA_half = (lane >> 4);
    uint32_t baseA[4];
    #pragma unroll
    for (int mi = 0; mi < 4; mi++) baseA[mi] = smA + (uint32_t)((rA + mi * 16) * 256);

    // B via x4 over ni-pairs
    int rB = wc * 32 + ((lane >> 4) & 1) * 8 + (lane & 7);   // + pi*16
    uint32_t xorB = (uint32_t)((lane & 7) << 4);
    int kbB_half = (lane >> 3) & 1;
    uint32_t baseB0[2], baseB1[2];
    #pragma unroll
    for (int pi = 0; pi < 2; pi++) {
        baseB0[pi] = smB0 + (uint32_t)((rB + pi * 16) * 256);
        baseB1[pi] = smB1 + (uint32_t)((rB + pi * 16) * 256);
    }

    int g = lane >> 2, th = lane & 3;
    float rsum[4][2];
    #pragma unroll
    for (int i = 0; i < 4; i++) { rsum[i][0] = 0.0f; rsum[i][1] = 0.0f; }

    float acc[4][4][4];

#define EPILOGUE(COL0, MODE, COLSCR) do {                                      \
    float csum[4][2];                                                          \
    _Pragma("unroll")                                                          \
    for (int i = 0; i < 4; i++) { csum[i][0] = 0.0f; csum[i][1] = 0.0f; }      \
    _Pragma("unroll")                                                          \
    for (int mi = 0; mi < 4; mi++) {                                           \
        int gi_b = row0 + wr * 64 + mi * 16 + g;                               \
        _Pragma("unroll")                                                      \
        for (int ni = 0; ni < 4; ni++) {                                       \
            int gj_b = (COL0) + wc * 32 + ni * 8 + th * 2;                     \
            _Pragma("unroll")                                                  \
            for (int e = 0; e < 4; e++) {                                      \
                int h = e >> 1, p = e & 1;                                     \
                float v = acc[mi][ni][e];                                      \
                if ((MODE) == 2 && (gj_b + p) == (gi_b + h * 8) + NN)          \
                    g_partner[gi_b + h * 8] = v;                               \
                float ex = exp2f(v - CB2);                                     \
                if ((MODE) == 1 && (gj_b + p) <= (gi_b + h * 8)) ex = 0.0f;    \
                rsum[mi][h] += ex;                                             \
                csum[ni][p] += ex;                                             \
            }                                                                  \
        }                                                                      \
    }                                                                          \
    _Pragma("unroll")                                                          \
    for (int ni = 0; ni < 4; ni++)                                             \
        _Pragma("unroll")                                                      \
        for (int p = 0; p < 2; p++) {                                          \
            float v = csum[ni][p];                                             \
            v += __shfl_xor_sync(0xffffffffu, v, 4);                           \
            v += __shfl_xor_sync(0xffffffffu, v, 8);                           \
            v += __shfl_xor_sync(0xffffffffu, v, 16);                          \
            if (lane < 4)                                                      \
                (COLSCR)[(wc * 32 + ni * 8 + lane * 2 + p) * 2 + wr] = v;      \
        }                                                                      \
} while (0)

    // ---- tile 0 ----
    CP_WAIT(1);
    __syncthreads();
    if (m0 != 0) {
        #pragma unroll
        for (int mi = 0; mi < 4; mi++)
            #pragma unroll
            for (int ni = 0; ni < 4; ni++)
                #pragma unroll
                for (int e = 0; e < 4; e++) acc[mi][ni][e] = 0.0f;
        gemm_tile(baseA, baseB0, xorA, xorB, kbA_half, kbB_half, acc);
        if (m0 == 1) { EPILOGUE(col0_0, 1, colscr0); }
        else if (m0 == 2) { EPILOGUE(col0_0, 2, colscr0); }
        else { EPILOGUE(col0_0, 3, colscr0); }
    }

    // ---- tile 1 ----
    CP_WAIT(0);
    __syncthreads();
    #pragma unroll
    for (int mi = 0; mi < 4; mi++)
        #pragma unroll
        for (int ni = 0; ni < 4; ni++)
            #pragma unroll
            for (int e = 0; e < 4; e++) acc[mi][ni][e] = 0.0f;
    gemm_tile(baseA, baseB1, xorA, xorB, kbA_half, kbB_half, acc);
    if (m1 == 1) { EPILOGUE(col0_1, 1, colscr1); }
    else if (m1 == 2) { EPILOGUE(col0_1, 2, colscr1); }
    else { EPILOGUE(col0_1, 3, colscr1); }
#undef EPILOGUE

    // ---- row sums (accumulated over both tiles) -> rowscr ----
    #pragma unroll
    for (int mi = 0; mi < 4; mi++)
        #pragma unroll
        for (int h = 0; h < 2; h++) {
            float v = rsum[mi][h];
            v += __shfl_xor_sync(0xffffffffu, v, 1);
            v += __shfl_xor_sync(0xffffffffu, v, 2);
            if (th == 0)
                rowscr[(wr * 64 + mi * 16 + g + h * 8) * 4 + wc] = v;
        }
    __syncthreads();

    if (tid < 128) {
        float s = rowscr[tid * 4] + rowscr[tid * 4 + 1]
                + rowscr[tid * 4 + 2] + rowscr[tid * 4 + 3];
        atomicAdd(&g_rowsum[row0 + tid], s);
    } else {
        int c = tid - 128;
        if (m0 != 0) {
            float s0 = colscr0[c * 2] + colscr0[c * 2 + 1];
            atomicAdd(&g_rowsum[col0_0 + c], s0);
        }
        float s1 = colscr1[c * 2] + colscr1[c * 2 + 1];
        atomicAdd(&g_rowsum[col0_1 + c], s1);
    }

    // ---- last CTA finalizes ----
    __threadfence();
    __syncthreads();
    __shared__ unsigned int s_last;
    if (tid == 0) s_last = (atomicAdd(&g_done, 1u) == NCTAS - 1) ? 1u : 0u;
    __syncthreads();
    if (s_last) {
        float local = 0.0f;
        #pragma unroll 4
        for (int j = 0; j < 32; j++) {
            int i = tid + j * 256;
            float u = g_partner[(i < NN) ? i : i - NN];
            float pos2 = 2.0f * u;                       // log2 domain
            float lse = logf(g_rowsum[i] + exp2f(pos2 - CB2)) + 10.0f;
            local += lse - pos2 * LN2;
        }
        #pragma unroll
        for (int o = 16; o; o >>= 1) local += __shfl_xor_sync(0xffffffffu, local, o);
        if (lane == 0) rowscr[wid] = local;
        __syncthreads();
        if (tid == 0) {
            float v = 0.0f;
            #pragma unroll
            for (int w = 0; w < 8; w++) v += rowscr[w];
            out[0] = v / ((float)MM * (float)MM);
        }
    }
}

extern "C" void kernel_launch(void* const* d_in, const int* in_sizes, int n_in,
                              void* d_out, int out_size) {
    const float* z1 = (const float*)d_in[0];
    const float* z2 = (const float*)d_in[1];
    float* out = (float*)d_out;

    cudaFuncSetAttribute(sim_kernel, cudaFuncAttributeMaxDynamicSharedMemorySize, 102400);

    normalize_kernel<<<NN / 16, 512>>>(z1, z2);
    sim_kernel<<<NCTAS, 256, 102400>>>(out);
}